// round 6
// baseline (speedup 1.0000x reference)
#include <cuda_runtime.h>
#include <cuda_bf16.h>

// ALiBi: out[b,h,i,j] = scores[b,h,i,j] + (j - i) * slopes[h]
// B=2, H=16, S=2048. Pure HBM streaming: 512 MiB in + 512 MiB out.
//
// R5: persistent grid (one wave, 148 SMs x 4 CTAs = 592 blocks) with a
// grid-stride loop over row-tiles. Per-iteration body = R3's best config:
// 4 rows/tile, 128 lanes/row, 4 independent front-batched float4 loads per
// thread, streaming cache hints. Removes all wave-transition dead time.

static constexpr int S = 2048;
static constexpr int H = 16;
static constexpr int THREADS = 512;
static constexpr int ROWS_PER_TILE = 4;       // 512 threads / 128 lanes-per-row
static constexpr int LANES_PER_ROW = 128;
static constexpr int UNROLL = 4;              // float4s per thread per tile
static constexpr int PERSISTENT_BLOCKS = 592; // 148 SMs * 4 CTAs

__global__ void __launch_bounds__(THREADS, 4)
alibi_kernel(const float* __restrict__ scores,
             const float* __restrict__ slopes,
             float* __restrict__ out,
             int num_tiles)
{
    const int tid  = threadIdx.x;
    const int lane = tid & (LANES_PER_ROW - 1);       // 0..127
    const int rib  = tid >> 7;                        // row within tile, 0..3
    const int j0   = lane * 4;                        // first column this thread owns

    for (int tile = blockIdx.x; tile < num_tiles; tile += PERSISTENT_BLOCKS) {
        const unsigned row = (unsigned)tile * ROWS_PER_TILE + rib;
        const int i = row & (S - 1);
        const int h = (row >> 11) & (H - 1);
        const float slope = __ldg(&slopes[h]);

        const size_t base = (size_t)row * S + j0;
        const float4* __restrict__ src = reinterpret_cast<const float4*>(scores + base);
        float4*       __restrict__ dst = reinterpret_cast<float4*>(out + base);

        // Front-batch 4 independent loads -> 4 outstanding DRAM requests
        float4 v[UNROLL];
#pragma unroll
        for (int k = 0; k < UNROLL; k++)
            v[k] = __ldcs(src + k * LANES_PER_ROW);   // stride 128 float4 = 512 floats

        // bias = (j - i) * slope
#pragma unroll
        for (int k = 0; k < UNROLL; k++) {
            const float d0 = (float)(j0 + k * (LANES_PER_ROW * 4) - i);
            v[k].x = fmaf(d0,        slope, v[k].x);
            v[k].y = fmaf(d0 + 1.0f, slope, v[k].y);
            v[k].z = fmaf(d0 + 2.0f, slope, v[k].z);
            v[k].w = fmaf(d0 + 3.0f, slope, v[k].w);
        }

#pragma unroll
        for (int k = 0; k < UNROLL; k++)
            __stcs(dst + k * LANES_PER_ROW, v[k]);
    }
}

extern "C" void kernel_launch(void* const* d_in, const int* in_sizes, int n_in,
                              void* d_out, int out_size)
{
    const float* scores = (const float*)d_in[0];
    const float* slopes = (const float*)d_in[1];
    float* out = (float*)d_out;

    const long long total = (long long)out_size;              // B*H*S*S
    const int rows = (int)(total / S);                        // 65536
    const int num_tiles = rows / ROWS_PER_TILE;               // 16384

    const int blocks = (num_tiles < PERSISTENT_BLOCKS) ? num_tiles : PERSISTENT_BLOCKS;
    alibi_kernel<<<blocks, THREADS>>>(scores, slopes, out, num_tiles);
}

// round 7
// speedup vs baseline: 1.1258x; 1.1258x over previous
#include <cuda_runtime.h>
#include <cuda_bf16.h>

// ALiBi: out[b,h,i,j] = scores[b,h,i,j] + (j - i) * slopes[h]
// B=2, H=16, S=2048. Pure HBM streaming: 512 MiB in + 512 MiB out.
//
// R6 = revert to R3 (best: 156.1us, 6.79 TB/s). The kernel is pinned at the
// B300 chip-wide LTS throughput cap (~6300 B/cyc, path-independent): measured
// bandwidth is invariant to MLP (4 vs 8) and occupancy (72% vs 39%), and
// 1 GiB / 6.79 TB/s = 158us matches wallclock. Traffic is irreducible, so
// this is the converged configuration.
//
// Config: 4 rows per 512-thread block, 128 lanes/row, 4 independent
// front-batched float4 loads per thread (MLP_p1=4), streaming cache hints.

static constexpr int S = 2048;
static constexpr int H = 16;
static constexpr int THREADS = 512;
static constexpr int ROWS_PER_BLOCK = 4;      // 512 threads / 128 lanes-per-row
static constexpr int LANES_PER_ROW = 128;
static constexpr int UNROLL = 4;              // float4s per thread (one row = 128*4 float4)

__global__ void __launch_bounds__(THREADS, 4)
alibi_kernel(const float* __restrict__ scores,
             const float* __restrict__ slopes,
             float* __restrict__ out)
{
    const int tid  = threadIdx.x;
    const int lane = tid & (LANES_PER_ROW - 1);       // 0..127
    const int rib  = tid >> 7;                        // row within block, 0..3

    const unsigned row = blockIdx.x * ROWS_PER_BLOCK + rib;
    const int i = row & (S - 1);
    const int h = (row >> 11) & (H - 1);
    const float slope = __ldg(&slopes[h]);

    // This thread's 4 float4s: columns j0 + k*512 floats (k=0..3), same row.
    const int j0 = lane * 4;
    const size_t base = (size_t)row * S + j0;

    const float4* __restrict__ src = reinterpret_cast<const float4*>(scores + base);
    float4*       __restrict__ dst = reinterpret_cast<float4*>(out + base);

    // Front-batch all 4 independent loads -> 4 outstanding DRAM requests
    float4 v[UNROLL];
#pragma unroll
    for (int k = 0; k < UNROLL; k++)
        v[k] = __ldcs(src + k * LANES_PER_ROW);       // stride 128 float4 = 512 floats

    // bias = (j - i) * slope
#pragma unroll
    for (int k = 0; k < UNROLL; k++) {
        const float d0 = (float)(j0 + k * (LANES_PER_ROW * 4) - i);
        v[k].x = fmaf(d0,        slope, v[k].x);
        v[k].y = fmaf(d0 + 1.0f, slope, v[k].y);
        v[k].z = fmaf(d0 + 2.0f, slope, v[k].z);
        v[k].w = fmaf(d0 + 3.0f, slope, v[k].w);
    }

#pragma unroll
    for (int k = 0; k < UNROLL; k++)
        __stcs(dst + k * LANES_PER_ROW, v[k]);
}

extern "C" void kernel_launch(void* const* d_in, const int* in_sizes, int n_in,
                              void* d_out, int out_size)
{
    const float* scores = (const float*)d_in[0];
    const float* slopes = (const float*)d_in[1];
    float* out = (float*)d_out;

    const long long total = (long long)out_size;          // B*H*S*S
    const int rows = (int)(total / S);                    // 65536
    const int blocks = rows / ROWS_PER_BLOCK;             // 16384

    alibi_kernel<<<blocks, THREADS>>>(scores, slopes, out);
}

// round 8
// speedup vs baseline: 1.1265x; 1.0006x over previous
#include <cuda_runtime.h>
#include <cuda_bf16.h>

// ALiBi: out[b,h,i,j] = scores[b,h,i,j] + (j - i) * slopes[h]
// B=2, H=16, S=2048. Pure HBM streaming: 512 MiB in + 512 MiB out.
//
// R7: final config-axis probe — 256-thread blocks (8 CTAs/SM, same warps/SM
// as R3's 512x4) to test whether CTA granularity / memory-controller burst
// interleave moves the 6.83 TB/s plateau. Expected NEUTRAL: bandwidth has
// been invariant to MLP (4 vs 8), occupancy (39% vs 74%), and grid shape
// (16K blocks vs persistent 592). 2 rows/block, 128 lanes/row, 4 independent
// front-batched float4 loads per thread, streaming cache hints.

static constexpr int S = 2048;
static constexpr int H = 16;
static constexpr int THREADS = 256;
static constexpr int ROWS_PER_BLOCK = 2;      // 256 threads / 128 lanes-per-row
static constexpr int LANES_PER_ROW = 128;
static constexpr int UNROLL = 4;              // float4s per thread (one row = 128*4 float4)

__global__ void __launch_bounds__(THREADS, 8)
alibi_kernel(const float* __restrict__ scores,
             const float* __restrict__ slopes,
             float* __restrict__ out)
{
    const int tid  = threadIdx.x;
    const int lane = tid & (LANES_PER_ROW - 1);       // 0..127
    const int rib  = tid >> 7;                        // row within block, 0..1

    const unsigned row = blockIdx.x * ROWS_PER_BLOCK + rib;
    const int i = row & (S - 1);
    const int h = (row >> 11) & (H - 1);
    const float slope = __ldg(&slopes[h]);

    // This thread's 4 float4s: columns j0 + k*512 floats (k=0..3), same row.
    const int j0 = lane * 4;
    const size_t base = (size_t)row * S + j0;

    const float4* __restrict__ src = reinterpret_cast<const float4*>(scores + base);
    float4*       __restrict__ dst = reinterpret_cast<float4*>(out + base);

    // Front-batch all 4 independent loads -> 4 outstanding DRAM requests
    float4 v[UNROLL];
#pragma unroll
    for (int k = 0; k < UNROLL; k++)
        v[k] = __ldcs(src + k * LANES_PER_ROW);       // stride 128 float4 = 512 floats

    // bias = (j - i) * slope
#pragma unroll
    for (int k = 0; k < UNROLL; k++) {
        const float d0 = (float)(j0 + k * (LANES_PER_ROW * 4) - i);
        v[k].x = fmaf(d0,        slope, v[k].x);
        v[k].y = fmaf(d0 + 1.0f, slope, v[k].y);
        v[k].z = fmaf(d0 + 2.0f, slope, v[k].z);
        v[k].w = fmaf(d0 + 3.0f, slope, v[k].w);
    }

#pragma unroll
    for (int k = 0; k < UNROLL; k++)
        __stcs(dst + k * LANES_PER_ROW, v[k]);
}

extern "C" void kernel_launch(void* const* d_in, const int* in_sizes, int n_in,
                              void* d_out, int out_size)
{
    const float* scores = (const float*)d_in[0];
    const float* slopes = (const float*)d_in[1];
    float* out = (float*)d_out;

    const long long total = (long long)out_size;          // B*H*S*S
    const int rows = (int)(total / S);                    // 65536
    const int blocks = rows / ROWS_PER_BLOCK;             // 32768

    alibi_kernel<<<blocks, THREADS>>>(scores, slopes, out);
}